// round 1
// baseline (speedup 1.0000x reference)
#include <cuda_runtime.h>
#include <math.h>

#define S_LEN  2048
#define B_SZ   2
#define DMODEL 1024
#define NH     16
#define DK     64
#define MTOT   (B_SZ * S_LEN)   // 4096 rows

// Scratch (static __device__ arrays: allocation-free per harness rules)
__device__ float g_Q[MTOT * DMODEL];   // 16 MB  [B,S, H*Dk]
__device__ float g_K[MTOT * DK];       // 1 MB   [B,S, Dk]
__device__ float g_V[MTOT * DK];       // 1 MB
__device__ float g_AO[MTOT * DMODEL];  // 16 MB  attention output, [B,S, H*Dk]

// ---------------------------------------------------------------------------
// Generic GEMM + bias: C[M,N] = A[M,K] @ B[K,N] + bias[N]
// BM=BN=64, BK=16, 256 threads, 4x4 register micro-tile per thread.
// Requires: M%64==0, N%64==0, K%16==0 (true for all uses here).
// ---------------------------------------------------------------------------
__global__ __launch_bounds__(256) void gemm_bias_kernel(
    const float* __restrict__ A, const float* __restrict__ Bm,
    const float* __restrict__ bias, float* __restrict__ C,
    int M, int N, int K)
{
    __shared__ float As[16][68];   // [k][m], padded
    __shared__ float Bs[16][68];   // [k][n], padded (68%4==0 keeps float4 align)

    const int t  = threadIdx.x;
    const int tx = t & 15;
    const int ty = t >> 4;
    const int bm = blockIdx.x * 64;
    const int bn = blockIdx.y * 64;

    const int a_row = t >> 2;     // 0..63
    const int a_c4  = t & 3;      // 0..3  (k-chunk of 4)
    const int b_row = t >> 4;     // 0..15 (k)
    const int b_c4  = t & 15;     // 0..15 (n-chunk of 4)

    float acc[4][4];
#pragma unroll
    for (int i = 0; i < 4; i++)
#pragma unroll
        for (int j = 0; j < 4; j++) acc[i][j] = 0.0f;

    for (int k0 = 0; k0 < K; k0 += 16) {
        // Load A tile [64 x 16], store transposed As[k][m]
        float4 av = *(const float4*)&A[(size_t)(bm + a_row) * K + k0 + a_c4 * 4];
        As[a_c4 * 4 + 0][a_row] = av.x;
        As[a_c4 * 4 + 1][a_row] = av.y;
        As[a_c4 * 4 + 2][a_row] = av.z;
        As[a_c4 * 4 + 3][a_row] = av.w;
        // Load B tile [16 x 64] direct
        float4 bv = *(const float4*)&Bm[(size_t)(k0 + b_row) * N + bn + b_c4 * 4];
        *(float4*)&Bs[b_row][b_c4 * 4] = bv;
        __syncthreads();

#pragma unroll
        for (int k = 0; k < 16; k++) {
            float4 a4 = *(const float4*)&As[k][ty * 4];
            float4 b4 = *(const float4*)&Bs[k][tx * 4];
            float a[4] = {a4.x, a4.y, a4.z, a4.w};
            float b[4] = {b4.x, b4.y, b4.z, b4.w};
#pragma unroll
            for (int i = 0; i < 4; i++)
#pragma unroll
                for (int j = 0; j < 4; j++)
                    acc[i][j] = fmaf(a[i], b[j], acc[i][j]);
        }
        __syncthreads();
    }

    float4 bb = *(const float4*)&bias[bn + tx * 4];
    float bj[4] = {bb.x, bb.y, bb.z, bb.w};
#pragma unroll
    for (int i = 0; i < 4; i++) {
        float4 o;
        o.x = acc[i][0] + bj[0];
        o.y = acc[i][1] + bj[1];
        o.z = acc[i][2] + bj[2];
        o.w = acc[i][3] + bj[3];
        *(float4*)&C[(size_t)(bm + ty * 4 + i) * N + bn + tx * 4] = o;
    }
}

// ---------------------------------------------------------------------------
// Fused MQA flash attention.
// grid = (S/64, NH, B), block = 256 (16x16, 4x4 micro-tiles)
// Q tile 64 queries x 64 dims; stream K/V in 64-key tiles with online softmax.
// Smem (dynamic, 65792 B):
//   Qs[d][q]  4096 f   (d-major, pre-scaled by 1/sqrt(Dk))
//   Ks[d][k]  4096 f   (d-major)
//   Vs[k][d]  4096 f
//   Ps[k][q]  64*65 f  (padded to kill store conflicts)
// ---------------------------------------------------------------------------
__global__ __launch_bounds__(256) void mqa_flash_kernel()
{
    extern __shared__ float sm[];
    float* Qs = sm;             // 4096
    float* Ks = sm + 4096;      // 4096
    float* Vs = sm + 8192;      // 4096
    float* Ps = sm + 12288;     // 64*65 = 4160

    const int t  = threadIdx.x;
    const int tx = t & 15;
    const int ty = t >> 4;
    const int qt = blockIdx.x;
    const int h  = blockIdx.y;
    const int b  = blockIdx.z;

    const float* Qg = g_Q + ((size_t)(b * S_LEN + qt * 64)) * DMODEL + h * DK;

    // Load Q tile transposed (d-major), pre-scaled by 1/sqrt(64) = 0.125
#pragma unroll
    for (int r = 0; r < 4; r++) {
        int idx = t + r * 256;
        int q   = idx >> 4;
        int c4  = idx & 15;
        float4 v = *(const float4*)&Qg[(size_t)q * DMODEL + c4 * 4];
        Qs[(c4 * 4 + 0) * 64 + q] = v.x * 0.125f;
        Qs[(c4 * 4 + 1) * 64 + q] = v.y * 0.125f;
        Qs[(c4 * 4 + 2) * 64 + q] = v.z * 0.125f;
        Qs[(c4 * 4 + 3) * 64 + q] = v.w * 0.125f;
    }

    float m_i[4], l_i[4], o[4][4];
#pragma unroll
    for (int i = 0; i < 4; i++) {
        m_i[i] = -1e30f;
        l_i[i] = 0.0f;
#pragma unroll
        for (int j = 0; j < 4; j++) o[i][j] = 0.0f;
    }

    for (int kt = 0; kt < S_LEN / 64; kt++) {
        const float* Kg = g_K + (size_t)(b * S_LEN + kt * 64) * DK;
        const float* Vg = g_V + (size_t)(b * S_LEN + kt * 64) * DK;

        __syncthreads();  // previous iteration's reads of Ks/Vs/Ps complete
#pragma unroll
        for (int r = 0; r < 4; r++) {
            int idx  = t + r * 256;
            int krow = idx >> 4;
            int c4   = idx & 15;
            float4 kv = *(const float4*)&Kg[(size_t)krow * DK + c4 * 4];
            Ks[(c4 * 4 + 0) * 64 + krow] = kv.x;
            Ks[(c4 * 4 + 1) * 64 + krow] = kv.y;
            Ks[(c4 * 4 + 2) * 64 + krow] = kv.z;
            Ks[(c4 * 4 + 3) * 64 + krow] = kv.w;
            float4 vv = *(const float4*)&Vg[(size_t)krow * DK + c4 * 4];
            *(float4*)&Vs[krow * 64 + c4 * 4] = vv;
        }
        __syncthreads();

        // S = (Q/sqrt(Dk)) @ K^T   (64x64, reduce over d=64)
        float s[4][4];
#pragma unroll
        for (int i = 0; i < 4; i++)
#pragma unroll
            for (int j = 0; j < 4; j++) s[i][j] = 0.0f;

#pragma unroll 8
        for (int d = 0; d < DK; d++) {
            float4 a4 = *(const float4*)&Qs[d * 64 + ty * 4];
            float4 k4 = *(const float4*)&Ks[d * 64 + tx * 4];
            float a[4] = {a4.x, a4.y, a4.z, a4.w};
            float kk[4] = {k4.x, k4.y, k4.z, k4.w};
#pragma unroll
            for (int i = 0; i < 4; i++)
#pragma unroll
                for (int j = 0; j < 4; j++)
                    s[i][j] = fmaf(a[i], kk[j], s[i][j]);
        }

        // Online softmax per query row (row owned by 16 threads sharing ty)
#pragma unroll
        for (int i = 0; i < 4; i++) {
            float mx = s[i][0];
            mx = fmaxf(mx, s[i][1]);
            mx = fmaxf(mx, s[i][2]);
            mx = fmaxf(mx, s[i][3]);
#pragma unroll
            for (int off = 1; off < 16; off <<= 1)
                mx = fmaxf(mx, __shfl_xor_sync(0xffffffffu, mx, off));
            float mnew = fmaxf(m_i[i], mx);
            float corr = __expf(m_i[i] - mnew);
            m_i[i] = mnew;
            float rs = 0.0f;
#pragma unroll
            for (int j = 0; j < 4; j++) {
                float p = __expf(s[i][j] - mnew);
                s[i][j] = p;
                rs += p;
            }
#pragma unroll
            for (int off = 1; off < 16; off <<= 1)
                rs += __shfl_xor_sync(0xffffffffu, rs, off);
            l_i[i] = l_i[i] * corr + rs;
#pragma unroll
            for (int j = 0; j < 4; j++) {
                o[i][j] *= corr;
                Ps[(tx * 4 + j) * 65 + ty * 4 + i] = s[i][j];
            }
        }
        __syncthreads();

        // O += P @ V   (64x64, reduce over k=64)
#pragma unroll 8
        for (int k = 0; k < 64; k++) {
            float4 v4 = *(const float4*)&Vs[k * 64 + tx * 4];
            float vv[4] = {v4.x, v4.y, v4.z, v4.w};
            float pp[4];
#pragma unroll
            for (int i = 0; i < 4; i++) pp[i] = Ps[k * 65 + ty * 4 + i];
#pragma unroll
            for (int i = 0; i < 4; i++)
#pragma unroll
                for (int j = 0; j < 4; j++)
                    o[i][j] = fmaf(pp[i], vv[j], o[i][j]);
        }
    }

    // Normalize and write to g_AO[b, s, h*64 + d]
#pragma unroll
    for (int i = 0; i < 4; i++) {
        float inv = 1.0f / l_i[i];
        size_t row = (size_t)(b * S_LEN + qt * 64 + ty * 4 + i) * DMODEL + h * DK + tx * 4;
        float4 ov;
        ov.x = o[i][0] * inv;
        ov.y = o[i][1] * inv;
        ov.z = o[i][2] * inv;
        ov.w = o[i][3] * inv;
        *(float4*)&g_AO[row] = ov;
    }
}

// ---------------------------------------------------------------------------
extern "C" void kernel_launch(void* const* d_in, const int* in_sizes, int n_in,
                              void* d_out, int out_size)
{
    const float* x  = (const float*)d_in[0];
    const float* Wq = (const float*)d_in[1];
    const float* bq = (const float*)d_in[2];
    const float* Wk = (const float*)d_in[3];
    const float* bk = (const float*)d_in[4];
    const float* Wv = (const float*)d_in[5];
    const float* bv = (const float*)d_in[6];
    const float* Wo = (const float*)d_in[7];
    const float* bo = (const float*)d_in[8];
    float* out = (float*)d_out;

    void *pQ, *pK, *pV, *pAO;
    cudaGetSymbolAddress(&pQ,  g_Q);
    cudaGetSymbolAddress(&pK,  g_K);
    cudaGetSymbolAddress(&pV,  g_V);
    cudaGetSymbolAddress(&pAO, g_AO);

    const int SMEM_ATTN = 16448 * 4;  // 65792 bytes
    cudaFuncSetAttribute(mqa_flash_kernel,
                         cudaFuncAttributeMaxDynamicSharedMemorySize, SMEM_ATTN);

    // Projections
    gemm_bias_kernel<<<dim3(MTOT / 64, DMODEL / 64), 256>>>(
        x, Wq, bq, (float*)pQ, MTOT, DMODEL, DMODEL);
    gemm_bias_kernel<<<dim3(MTOT / 64, 1), 256>>>(
        x, Wk, bk, (float*)pK, MTOT, DK, DMODEL);
    gemm_bias_kernel<<<dim3(MTOT / 64, 1), 256>>>(
        x, Wv, bv, (float*)pV, MTOT, DK, DMODEL);

    // Fused MQA flash attention
    mqa_flash_kernel<<<dim3(S_LEN / 64, NH, B_SZ), 256, SMEM_ATTN>>>();

    // Output projection
    gemm_bias_kernel<<<dim3(MTOT / 64, DMODEL / 64), 256>>>(
        (const float*)pAO, Wo, bo, out, MTOT, DMODEL, DMODEL);
}